// round 11
// baseline (speedup 1.0000x reference)
#include <cuda_runtime.h>
#include <cuda_bf16.h>
#include <cstdint>

// ---------------------------------------------------------------------------
// Problem constants
// ---------------------------------------------------------------------------
#define D_IN   128
#define WID    512
#define NSEG   256
#define HEADS  8
#define DPD    128
#define COMB   (D_IN + WID)
#define RCP_TAB 4096
#define NMAX 131072

// ---------------------------------------------------------------------------
// Device global scratch (no runtime allocation)
// ---------------------------------------------------------------------------
__device__ int8_t g_x8h[(size_t)NMAX * D_IN], g_x8l[(size_t)NMAX * D_IN];
__device__ int8_t g_a8h[(size_t)NMAX * WID], g_a8l[(size_t)NMAX * WID];
__device__ __nv_bfloat16 g_hh[(size_t)NMAX * WID], g_hl[(size_t)NMAX * WID];
__device__ int8_t g_w1h[WID * D_IN], g_w1l[WID * D_IN];
__device__ int8_t g_w2h[WID * WID], g_w2l[WID * WID];
__device__ int8_t g_w3h[WID * WID], g_w3l[WID * WID];
__device__ int8_t g_wrh[WID * WID], g_wrl[WID * WID];
__device__ float g_sx[NMAX], g_sa[NMAX];
__device__ float g_sw1[WID], g_sw2[WID], g_sw3[WID], g_sw4[WID];
__device__ float g_z[(size_t)NMAX * WID];
__device__ float g_agg[(size_t)NMAX * WID];
__device__ float g_weff[COMB * HEADS];
__device__ int   g_segstart[NSEG + 1];
__device__ float g_rcp[RCP_TAB];

// ---------------------------------------------------------------------------
// PTX primitives (non-arch-specific; valid on plain sm_100)
// ---------------------------------------------------------------------------
__device__ __forceinline__ uint32_t smem_u32(const void* p) {
    uint32_t a;
    asm("{ .reg .u64 t; cvta.to.shared.u64 t, %1; cvt.u32.u64 %0, t; }" : "=r"(a) : "l"(p));
    return a;
}

#define CP_ASYNC16(dst, src) \
    asm volatile("cp.async.cg.shared.global [%0], [%1], 16;" :: "r"(dst), "l"(src))
#define CP_COMMIT() asm volatile("cp.async.commit_group;" ::: "memory")
#define CP_WAIT1()  asm volatile("cp.async.wait_group 1;" ::: "memory")
#define CP_WAIT0()  asm volatile("cp.async.wait_group 0;" ::: "memory")

#define LDSM_X4(r, addr) \
    asm volatile("ldmatrix.sync.aligned.m8n8.x4.shared.b16 {%0,%1,%2,%3}, [%4];" \
        : "=r"((r)[0]), "=r"((r)[1]), "=r"((r)[2]), "=r"((r)[3]) : "r"(addr))

// s8 MMA m16n8k32, s32 accum
__device__ __forceinline__ void mma_s8(int* d, const uint32_t* a, uint32_t b0, uint32_t b1) {
    asm volatile(
        "mma.sync.aligned.m16n8k32.row.col.s32.s8.s8.s32 "
        "{%0,%1,%2,%3}, {%4,%5,%6,%7}, {%8,%9}, {%0,%1,%2,%3};"
        : "+r"(d[0]), "+r"(d[1]), "+r"(d[2]), "+r"(d[3])
        : "r"(a[0]), "r"(a[1]), "r"(a[2]), "r"(a[3]), "r"(b0), "r"(b1));
}

// ---------------------------------------------------------------------------
// Small precompute kernels
// ---------------------------------------------------------------------------
__global__ void segstart_kernel(const int* __restrict__ segw, int M) {
    int s = threadIdx.x;
    if (s > NSEG) return;
    bool is64 = (segw[M - 1] == 0);   // int64: high half of last elem is 0
    int lo = 0, hi = M;
    while (lo < hi) {
        int mid = (lo + hi) >> 1;
        int v = is64 ? segw[2 * mid] : segw[mid];
        if (v < s) lo = mid + 1; else hi = mid;
    }
    g_segstart[s] = lo;
}

__global__ void rcp_init_kernel() {
    int i = blockIdx.x * blockDim.x + threadIdx.x;
    if (i < RCP_TAB) g_rcp[i] = 1.0f / (float)(i ? i : 1);
}

__global__ void weff_kernel(const float* __restrict__ Wk, const float* __restrict__ Wq) {
    int idx = blockIdx.x * blockDim.x + threadIdx.x;
    if (idx >= COMB * HEADS) return;
    int j = idx >> 3, h = idx & 7;
    const float* wk = Wk + (size_t)j * (HEADS * DPD) + h * DPD;
    const float* wq = Wq + h * DPD;
    float s = 0.f;
    #pragma unroll 8
    for (int d = 0; d < DPD; d++) s += wk[d] * wq[d];
    g_weff[idx] = s;
}

// ---------------------------------------------------------------------------
// Quantization helpers (round split: q = 256*ah + al, al zero-mean)
// ---------------------------------------------------------------------------
__global__ void quant_x_kernel(const float* __restrict__ X,
                               int8_t* __restrict__ qh, int8_t* __restrict__ ql,
                               float* __restrict__ s) {
    int row  = blockIdx.x * 8 + (threadIdx.x >> 5);
    int lane = threadIdx.x & 31;
    size_t base = (size_t)row * D_IN + lane * 4;
    float4 f = *(const float4*)(X + base);
    float v[4] = {f.x, f.y, f.z, f.w};
    float m = fmaxf(fmaxf(fabsf(v[0]), fabsf(v[1])), fmaxf(fabsf(v[2]), fabsf(v[3])));
    #pragma unroll
    for (int off = 16; off; off >>= 1) m = fmaxf(m, __shfl_xor_sync(~0u, m, off));
    float inv = m > 0.f ? 32512.f / m : 0.f;
    if (lane == 0) s[row] = m * (1.f / 32512.f);
    uint32_t wh = 0, wl = 0;
    #pragma unroll
    for (int b = 0; b < 4; b++) {
        int q  = __float2int_rn(v[b] * inv);
        int ah = (q + 128) >> 8;
        int al = q - (ah << 8);
        wh |= (uint32_t)(ah & 0xFF) << (8 * b);
        wl |= (uint32_t)(al & 0xFF) << (8 * b);
    }
    *(uint32_t*)(qh + base) = wh;
    *(uint32_t*)(ql + base) = wl;
}

__global__ void quant_pair_kernel(const __nv_bfloat16* __restrict__ hi,
                                  const __nv_bfloat16* __restrict__ lo,
                                  int8_t* __restrict__ qh, int8_t* __restrict__ ql,
                                  float* __restrict__ s) {
    int row  = blockIdx.x * 8 + (threadIdx.x >> 5);
    int lane = threadIdx.x & 31;
    size_t base = (size_t)row * WID + lane * 16;
    const __nv_bfloat162* hp = (const __nv_bfloat162*)(hi + base);
    const __nv_bfloat162* lp = (const __nv_bfloat162*)(lo + base);
    float v[16];
    #pragma unroll
    for (int p = 0; p < 8; p++) {
        float2 h2 = __bfloat1622float2(hp[p]);
        float2 l2 = __bfloat1622float2(lp[p]);
        v[2 * p]     = h2.x + l2.x;
        v[2 * p + 1] = h2.y + l2.y;
    }
    float m = 0.f;
    #pragma unroll
    for (int i = 0; i < 16; i++) m = fmaxf(m, fabsf(v[i]));
    #pragma unroll
    for (int off = 16; off; off >>= 1) m = fmaxf(m, __shfl_xor_sync(~0u, m, off));
    float inv = m > 0.f ? 32512.f / m : 0.f;
    if (lane == 0) s[row] = m * (1.f / 32512.f);
    uint32_t ph[4], pl[4];
    #pragma unroll
    for (int g = 0; g < 4; g++) {
        uint32_t wh = 0, wl = 0;
        #pragma unroll
        for (int b = 0; b < 4; b++) {
            int q  = __float2int_rn(v[g * 4 + b] * inv);
            int ah = (q + 128) >> 8;
            int al = q - (ah << 8);
            wh |= (uint32_t)(ah & 0xFF) << (8 * b);
            wl |= (uint32_t)(al & 0xFF) << (8 * b);
        }
        ph[g] = wh; pl[g] = wl;
    }
    *(uint4*)(qh + base) = make_uint4(ph[0], ph[1], ph[2], ph[3]);
    *(uint4*)(ql + base) = make_uint4(pl[0], pl[1], pl[2], pl[3]);
}

__global__ void wquant_kernel(const float* __restrict__ W, int K,
                              int8_t* __restrict__ qh, int8_t* __restrict__ ql,
                              float* __restrict__ s) {
    int n = blockIdx.x;
    int tid = threadIdx.x;                 // 128 threads
    float m = 0.f;
    for (int k = tid; k < K; k += 128) m = fmaxf(m, fabsf(W[(size_t)k * WID + n]));
    __shared__ float red[128];
    red[tid] = m; __syncthreads();
    for (int st = 64; st; st >>= 1) {
        if (tid < st) red[tid] = fmaxf(red[tid], red[tid + st]);
        __syncthreads();
    }
    float mx = red[0];
    float inv = mx > 0.f ? 32512.f / mx : 0.f;
    if (tid == 0) s[n] = mx * (1.f / 32512.f);
    for (int k = tid; k < K; k += 128) {
        int q  = __float2int_rn(W[(size_t)k * WID + n] * inv);
        int ah = (q + 128) >> 8;
        qh[(size_t)n * K + k] = (int8_t)ah;
        ql[(size_t)n * K + k] = (int8_t)(q - (ah << 8));
    }
}

// ---------------------------------------------------------------------------
// INT8 split GEMM on mma.sync m16n8k32 (s32 accum).
//   CTA tile 128x128, 8 warps (4m x 2n), warp tile 32x64, K-chunk 64,
//   3-stage cp.async ring, 1 CTA/SM.  Warp tile widened to raise MAC per
//   smem-crossbar byte (24 -> 33).
//   acc1 = sum Ah*Bh ; acc2 = sum (Ah*Bl + Al*Bh)
//   D = sA[m]*sB[n]*(65536*acc1 + 256*acc2)
// ---------------------------------------------------------------------------
#define TS_B      80
#define T128_B    (128 * TS_B)              // 10240 (tile: 128 rows x 64 int8)
#define ST_AH     0
#define ST_AL     (T128_B)
#define ST_BH     (2 * T128_B)
#define ST_BL     (3 * T128_B)
#define STAGE_B   (4 * T128_B)              // 40960
#define NSTAGE    3
#define GEMM_SMEM (NSTAGE * STAGE_B)        // 122880
#define EPI_STW   136                       // bf16 stride (272 B) for staging

template<int MODE>
__global__ __launch_bounds__(256, 1)
void s8_gemm(const int8_t* __restrict__ Ah, const int8_t* __restrict__ Al,
             const int8_t* __restrict__ Bh, const int8_t* __restrict__ Bl,
             const float* __restrict__ sA, const float* __restrict__ sB,
             const float* __restrict__ bias,
             __nv_bfloat16* __restrict__ Ohi, __nv_bfloat16* __restrict__ Olo,
             float* __restrict__ Of, int K) {
    extern __shared__ char smem[];
    const uint32_t sb = smem_u32(smem);

    const int tid    = threadIdx.x;
    const int wid    = tid >> 5;
    const int lane   = tid & 31;
    const int warp_m = wid >> 1;          // 0..3 -> m offset 32*warp_m
    const int warp_n = wid & 1;           // 0..1 -> n offset 64*warp_n
    const int m0 = blockIdx.y * 128;      // x fastest -> A panel shared in L2
    const int n0 = blockIdx.x * 128;

    // ---- load setup: per-thread pointers, advanced by +64 per chunk ----
    const int lr  = tid >> 2;             // 0..63
    const int lj  = (tid & 3) * 16;
    const size_t rowK64 = (size_t)64 * K; // +64 rows offset
    const int8_t* pAh = Ah + (size_t)(m0 + lr) * K + lj;
    const int8_t* pAl = Al + (size_t)(m0 + lr) * K + lj;
    const int8_t* pBh = Bh + (size_t)(n0 + lr) * K + lj;
    const int8_t* pBl = Bl + (size_t)(n0 + lr) * K + lj;
    const uint32_t dA0 = (uint32_t)(ST_AH + lr * TS_B + lj);
    const uint32_t dB0 = (uint32_t)(ST_BH + lr * TS_B + lj);

    // ---- compute setup ----
    const int lrow = lane & 15;
    const int lchk = (lane >> 4) * 16;
    const uint32_t aoff = (uint32_t)((warp_m * 32 + lrow) * TS_B + lchk);
    const uint32_t boff = (uint32_t)((warp_n * 64 + lrow) * TS_B + lchk);

    int acc1[2][8][4], acc2[2][8][4];     // [mb 16][nb n8][frag]
    #pragma unroll
    for (int i = 0; i < 2; i++)
        #pragma unroll
        for (int j = 0; j < 8; j++)
            #pragma unroll
            for (int q = 0; q < 4; q++) { acc1[i][j][q] = 0; acc2[i][j][q] = 0; }

    const int nch = K >> 6;               // 64-int8 chunks

    #define ISSUE_CHUNK(stg) do {                                     \
        uint32_t _b = sb + (stg) * STAGE_B;                           \
        CP_ASYNC16(_b + dA0,                        pAh);             \
        CP_ASYNC16(_b + dA0 + 64 * TS_B,            pAh + rowK64);    \
        CP_ASYNC16(_b + dA0 + T128_B,               pAl);             \
        CP_ASYNC16(_b + dA0 + T128_B + 64 * TS_B,   pAl + rowK64);    \
        CP_ASYNC16(_b + dB0,                        pBh);             \
        CP_ASYNC16(_b + dB0 + 64 * TS_B,            pBh + rowK64);    \
        CP_ASYNC16(_b + dB0 + T128_B,               pBl);             \
        CP_ASYNC16(_b + dB0 + T128_B + 64 * TS_B,   pBl + rowK64);    \
        pAh += 64; pAl += 64; pBh += 64; pBl += 64;                   \
        CP_COMMIT();                                                  \
    } while (0)

    ISSUE_CHUNK(0);
    if (nch > 1) ISSUE_CHUNK(1);

    int stg = 0;
    for (int c = 0; c < nch; c++) {
        if (c + 1 < nch) CP_WAIT1(); else CP_WAIT0();
        __syncthreads();                  // single sync per chunk
        if (c + 2 < nch) {
            int ns = stg + 2; if (ns >= NSTAGE) ns -= NSTAGE;
            ISSUE_CHUNK(ns);
        }

        const uint32_t stage = sb + stg * STAGE_B;
        const uint32_t sAh = stage + ST_AH + aoff;
        const uint32_t sAl = stage + ST_AL + aoff;
        const uint32_t sBh = stage + ST_BH + boff;
        const uint32_t sBl = stage + ST_BL + boff;
        #pragma unroll
        for (int ks = 0; ks < 2; ks++) {
            uint32_t bh_[4][4], bl_[4][4], ah_[2][4], al_[2][4];
            #pragma unroll
            for (int g = 0; g < 4; g++)
                LDSM_X4(bh_[g], sBh + g * (16 * TS_B) + ks * 32);
            #pragma unroll
            for (int mb = 0; mb < 2; mb++)
                LDSM_X4(ah_[mb], sAh + mb * (16 * TS_B) + ks * 32);
            #pragma unroll
            for (int g = 0; g < 4; g++)
                LDSM_X4(bl_[g], sBl + g * (16 * TS_B) + ks * 32);
            #pragma unroll
            for (int mb = 0; mb < 2; mb++)
                LDSM_X4(al_[mb], sAl + mb * (16 * TS_B) + ks * 32);

            // pass 1: acc1 += Ah*Bh
            #pragma unroll
            for (int mb = 0; mb < 2; mb++)
                #pragma unroll
                for (int nb = 0; nb < 8; nb++) {
                    const int g = nb >> 1, p = nb & 1;
                    mma_s8(acc1[mb][nb], ah_[mb], bh_[g][p], bh_[g][p + 2]);
                }
            // pass 2: acc2 += Ah*Bl
            #pragma unroll
            for (int mb = 0; mb < 2; mb++)
                #pragma unroll
                for (int nb = 0; nb < 8; nb++) {
                    const int g = nb >> 1, p = nb & 1;
                    mma_s8(acc2[mb][nb], ah_[mb], bl_[g][p], bl_[g][p + 2]);
                }
            // pass 3: acc2 += Al*Bh
            #pragma unroll
            for (int mb = 0; mb < 2; mb++)
                #pragma unroll
                for (int nb = 0; nb < 8; nb++) {
                    const int g = nb >> 1, p = nb & 1;
                    mma_s8(acc2[mb][nb], al_[mb], bh_[g][p], bh_[g][p + 2]);
                }
        }
        if (++stg == NSTAGE) stg = 0;
    }
    #undef ISSUE_CHUNK

    // ---------------- Epilogue ----------------
    const int gid  = lane >> 2;
    const int tid4 = lane & 3;
    float sa[2][2];
    #pragma unroll
    for (int mb = 0; mb < 2; mb++)
        #pragma unroll
        for (int half = 0; half < 2; half++)
            sa[mb][half] = sA[m0 + warp_m * 32 + mb * 16 + gid + half * 8];

    if (MODE == 0) {
        // Stage bf16 hi/lo tiles in smem, then fully-coalesced copy-out.
        __syncthreads();                  // mainloop done; reuse stage smem
        __nv_bfloat16* sh = (__nv_bfloat16*)smem;
        __nv_bfloat16* sl = (__nv_bfloat16*)(smem + 128 * (EPI_STW * 2));

        #pragma unroll
        for (int nb = 0; nb < 8; nb++) {
            const int cc  = warp_n * 64 + nb * 8 + tid4 * 2;
            const int col = n0 + cc;
            const float sb0 = sB[col], sb1 = sB[col + 1];
            const float b0 = bias[col], b1 = bias[col + 1];
            #pragma unroll
            for (int mb = 0; mb < 2; mb++) {
                #pragma unroll
                for (int half = 0; half < 2; half++) {
                    const int r = warp_m * 32 + mb * 16 + gid + half * 8;
                    const float ss = sa[mb][half];
                    float d0 = ss * sb0 * (65536.f * (float)acc1[mb][nb][2 * half]
                                           + 256.f * (float)acc2[mb][nb][2 * half]);
                    float d1 = ss * sb1 * (65536.f * (float)acc1[mb][nb][2 * half + 1]
                                           + 256.f * (float)acc2[mb][nb][2 * half + 1]);
                    float v0 = fmaxf(d0 + b0, 0.f);
                    float v1 = fmaxf(d1 + b1, 0.f);
                    __nv_bfloat162 hw, lw;
                    hw.x = __float2bfloat16(v0);
                    hw.y = __float2bfloat16(v1);
                    lw.x = __float2bfloat16(v0 - __bfloat162float(hw.x));
                    lw.y = __float2bfloat16(v1 - __bfloat162float(hw.y));
                    *(__nv_bfloat162*)(sh + r * EPI_STW + cc) = hw;
                    *(__nv_bfloat162*)(sl + r * EPI_STW + cc) = lw;
                }
            }
        }
        __syncthreads();

        // copy-out: warp owns 16 rows; per iter 2 rows x 16 chunks of 16B
        const int rhalf = lane >> 4;      // 0..1
        const int c16   = lane & 15;      // 16B chunk in 256B row
        #pragma unroll
        for (int it = 0; it < 8; it++) {
            const int r = wid * 16 + it * 2 + rhalf;
            const uint4 vh = *(const uint4*)(sh + r * EPI_STW + c16 * 8);
            const uint4 vl = *(const uint4*)(sl + r * EPI_STW + c16 * 8);
            const size_t gbase = (size_t)(m0 + r) * WID + n0 + c16 * 8;
            *(uint4*)(Ohi + gbase) = vh;
            *(uint4*)(Olo + gbase) = vl;
        }
    } else {
        #pragma unroll
        for (int nb = 0; nb < 8; nb++) {
            const int col = n0 + warp_n * 64 + nb * 8 + tid4 * 2;
            const float sb0 = sB[col], sb1 = sB[col + 1];
            #pragma unroll
            for (int mb = 0; mb < 2; mb++) {
                #pragma unroll
                for (int half = 0; half < 2; half++) {
                    const int row = m0 + warp_m * 32 + mb * 16 + gid + half * 8;
                    const float ss = sa[mb][half];
                    float d0 = ss * sb0 * (65536.f * (float)acc1[mb][nb][2 * half]
                                           + 256.f * (float)acc2[mb][nb][2 * half]);
                    float d1 = ss * sb1 * (65536.f * (float)acc1[mb][nb][2 * half + 1]
                                           + 256.f * (float)acc2[mb][nb][2 * half + 1]);
                    *(float2*)(Of + (size_t)row * WID + col) = make_float2(d0, d1);
                }
            }
        }
    }
}

// ---------------------------------------------------------------------------
// Segmented prefix-mean + bias + relu (z fp32 -> agg fp32)
// ---------------------------------------------------------------------------
__global__ void scan_kernel(const float* __restrict__ Z, const float* __restrict__ br,
                            float* __restrict__ Agg) {
    int seg = blockIdx.x;
    int col = blockIdx.y * blockDim.x + threadIdx.x;
    int s = g_segstart[seg];
    int e = g_segstart[seg + 1];
    float b = br[col];
    float run = 0.f;
    for (int n = s; n < e; n++) {
        run += Z[(size_t)n * WID + col];
        int cnt = n - s + 1;
        float m = (cnt < RCP_TAB) ? run * g_rcp[cnt] : run / (float)cnt;
        Agg[(size_t)n * WID + col] = fmaxf(m + b, 0.f);
    }
}

// ---------------------------------------------------------------------------
// Final projection: out[n,h] = ([X, agg] @ w_eff)[n,h] / sqrt(DPD)
// ---------------------------------------------------------------------------
__global__ __launch_bounds__(256)
void final_kernel(const float* __restrict__ X, const float* __restrict__ Agg,
                  float* __restrict__ out, int M) {
    __shared__ float ws[HEADS * COMB];
    for (int i = threadIdx.x; i < COMB * HEADS; i += blockDim.x) {
        int j = i >> 3, h = i & 7;
        ws[h * COMB + j] = g_weff[i];
    }
    __syncthreads();

    int warp = threadIdx.x >> 5;
    int lane = threadIdx.x & 31;
    int row  = blockIdx.x * 8 + warp;
    if (row >= M) return;

    const float* xr = X   + (size_t)row * D_IN;
    const float* ar = Agg + (size_t)row * WID;

    float acc[HEADS];
    #pragma unroll
    for (int h = 0; h < HEADS; h++) acc[h] = 0.f;

    #pragma unroll
    for (int t = 0; t < D_IN / 32; t++) {
        int j = t * 32 + lane;
        float v = xr[j];
        #pragma unroll
        for (int h = 0; h < HEADS; h++) acc[h] = fmaf(v, ws[h * COMB + j], acc[h]);
    }
    #pragma unroll
    for (int t = 0; t < WID / 32; t++) {
        int j = t * 32 + lane;
        float v = ar[j];
        #pragma unroll
        for (int h = 0; h < HEADS; h++) acc[h] = fmaf(v, ws[h * COMB + D_IN + j], acc[h]);
    }

    #pragma unroll
    for (int off = 16; off; off >>= 1)
        #pragma unroll
        for (int h = 0; h < HEADS; h++)
            acc[h] += __shfl_xor_sync(0xffffffffu, acc[h], off);

    if (lane < HEADS)
        out[(size_t)row * HEADS + lane] = acc[lane] * 0.08838834764831844f;
}

// ---------------------------------------------------------------------------
// Launch
// ---------------------------------------------------------------------------
extern "C" void kernel_launch(void* const* d_in, const int* in_sizes, int n_in,
                              void* d_out, int out_size) {
    const float* X   = (const float*)d_in[0];
    const int*   seg = (const int*)  d_in[1];
    const float* W1  = (const float*)d_in[2];
    const float* b1  = (const float*)d_in[3];
    const float* W2  = (const float*)d_in[4];
    const float* b2  = (const float*)d_in[5];
    const float* W3  = (const float*)d_in[6];
    const float* b3  = (const float*)d_in[7];
    const float* Wr  = (const float*)d_in[8];
    const float* br  = (const float*)d_in[9];
    const float* Wk  = (const float*)d_in[10];
    const float* Wq  = (const float*)d_in[11];
    float* out = (float*)d_out;

    const int M = in_sizes[0] / D_IN;

    int8_t *x8h, *x8l, *a8h, *a8l;
    int8_t *w1h, *w1l, *w2h, *w2l, *w3h, *w3l, *wrh, *wrl;
    __nv_bfloat16 *hh, *hl;
    float *sx, *sa, *sw1, *sw2, *sw3, *sw4, *z, *agg;
    cudaGetSymbolAddress((void**)&x8h, g_x8h); cudaGetSymbolAddress((void**)&x8l, g_x8l);
    cudaGetSymbolAddress((void**)&a8h, g_a8h); cudaGetSymbolAddress((void**)&a8l, g_a8l);
    cudaGetSymbolAddress((void**)&hh,  g_hh);  cudaGetSymbolAddress((void**)&hl,  g_hl);
    cudaGetSymbolAddress((void**)&w1h, g_w1h); cudaGetSymbolAddress((void**)&w1l, g_w1l);
    cudaGetSymbolAddress((void**)&w2h, g_w2h); cudaGetSymbolAddress((void**)&w2l, g_w2l);
    cudaGetSymbolAddress((void**)&w3h, g_w3h); cudaGetSymbolAddress((void**)&w3l, g_w3l);
    cudaGetSymbolAddress((void**)&wrh, g_wrh); cudaGetSymbolAddress((void**)&wrl, g_wrl);
    cudaGetSymbolAddress((void**)&sx,  g_sx);  cudaGetSymbolAddress((void**)&sa,  g_sa);
    cudaGetSymbolAddress((void**)&sw1, g_sw1); cudaGetSymbolAddress((void**)&sw2, g_sw2);
    cudaGetSymbolAddress((void**)&sw3, g_sw3); cudaGetSymbolAddress((void**)&sw4, g_sw4);
    cudaGetSymbolAddress((void**)&z,   g_z);   cudaGetSymbolAddress((void**)&agg, g_agg);

    cudaFuncSetAttribute(s8_gemm<0>, cudaFuncAttributeMaxDynamicSharedMemorySize, GEMM_SMEM);
    cudaFuncSetAttribute(s8_gemm<1>, cudaFuncAttributeMaxDynamicSharedMemorySize, GEMM_SMEM);

    const dim3 ggrid(WID / 128, M / 128);  // x fastest: 4 N-blocks share an A panel

    quant_x_kernel<<<M / 8, 256>>>(X, x8h, x8l, sx);
    wquant_kernel<<<WID, 128>>>(W1, D_IN, w1h, w1l, sw1);
    rcp_init_kernel<<<RCP_TAB / 256, 256>>>();

    // h1 = relu(X @ W1 + b1) -> bf16 pair
    s8_gemm<0><<<ggrid, 256, GEMM_SMEM>>>(x8h, x8l, w1h, w1l, sx, sw1, b1, hh, hl, nullptr, D_IN);
    quant_pair_kernel<<<M / 8, 256>>>(hh, hl, a8h, a8l, sa);
    wquant_kernel<<<WID, 128>>>(W2, WID, w2h, w2l, sw2);

    // h2 = relu(h1 @ W2 + b2)
    s8_gemm<0><<<ggrid, 256, GEMM_SMEM>>>(a8h, a8l, w2h, w2l, sa, sw2, b2, hh, hl, nullptr, WID);
    quant_pair_kernel<<<M / 8, 256>>>(hh, hl, a8h, a8l, sa);
    wquant_kernel<<<WID, 128>>>(W3, WID, w3h, w3l, sw3);

    // enc = relu(h2 @ W3 + b3)
    s8_gemm<0><<<ggrid, 256, GEMM_SMEM>>>(a8h, a8l, w3h, w3l, sa, sw3, b3, hh, hl, nullptr, WID);
    quant_pair_kernel<<<M / 8, 256>>>(hh, hl, a8h, a8l, sa);
    wquant_kernel<<<WID, 128>>>(Wr, WID, wrh, wrl, sw4);

    // z = enc @ Wr (fp32; bias+relu after scan — scan commutes with Wr)
    s8_gemm<1><<<ggrid, 256, GEMM_SMEM>>>(a8h, a8l, wrh, wrl, sa, sw4, nullptr, nullptr, nullptr, z, WID);

    segstart_kernel<<<1, NSEG + 1>>>(seg, M);
    weff_kernel<<<(COMB * HEADS + 127) / 128, 128>>>(Wk, Wq);

    // agg = relu(cumseg_mean(z) + br)
    scan_kernel<<<dim3(NSEG, WID / 256), 256>>>(z, br, agg);

    // out = [X, agg] @ w_eff / sqrt(DPD)
    final_kernel<<<M / 8, 256>>>(X, agg, out, M);
}

// round 12
// speedup vs baseline: 1.1619x; 1.1619x over previous
#include <cuda_runtime.h>
#include <cuda_fp16.h>
#include <cstdint>

// ---------------------------------------------------------------------------
// Problem constants
// ---------------------------------------------------------------------------
#define D_IN   128
#define WID    512
#define NSEG   256
#define HEADS  8
#define DPD    128
#define COMB   (D_IN + WID)
#define RCP_TAB 4096
#define NMAX 131072

// ---------------------------------------------------------------------------
// Device global scratch (no runtime allocation)
// ---------------------------------------------------------------------------
__device__ int8_t g_x8h[(size_t)NMAX * D_IN], g_x8l[(size_t)NMAX * D_IN];
__device__ int8_t g_a8h[(size_t)NMAX * WID], g_a8l[(size_t)NMAX * WID];
__device__ __half g_h16[(size_t)NMAX * WID];           // inter-layer activation (fp16)
__device__ __half g_z16[(size_t)NMAX * WID];           // z (fp16)
__device__ __half g_agg16[(size_t)NMAX * WID];         // agg (fp16)
__device__ int8_t g_w1h[WID * D_IN], g_w1l[WID * D_IN];
__device__ int8_t g_w2h[WID * WID], g_w2l[WID * WID];
__device__ int8_t g_w3h[WID * WID], g_w3l[WID * WID];
__device__ int8_t g_wrh[WID * WID], g_wrl[WID * WID];
__device__ float g_sx[NMAX], g_sa[NMAX];
__device__ float g_sw1[WID], g_sw2[WID], g_sw3[WID], g_sw4[WID];
__device__ float g_weff[COMB * HEADS];
__device__ int   g_segstart[NSEG + 1];
__device__ float g_rcp[RCP_TAB];

// ---------------------------------------------------------------------------
// PTX primitives (non-arch-specific; valid on plain sm_100)
// ---------------------------------------------------------------------------
__device__ __forceinline__ uint32_t smem_u32(const void* p) {
    uint32_t a;
    asm("{ .reg .u64 t; cvta.to.shared.u64 t, %1; cvt.u32.u64 %0, t; }" : "=r"(a) : "l"(p));
    return a;
}

#define CP_ASYNC16(dst, src) \
    asm volatile("cp.async.cg.shared.global [%0], [%1], 16;" :: "r"(dst), "l"(src))
#define CP_COMMIT() asm volatile("cp.async.commit_group;" ::: "memory")
#define CP_WAIT1()  asm volatile("cp.async.wait_group 1;" ::: "memory")
#define CP_WAIT0()  asm volatile("cp.async.wait_group 0;" ::: "memory")

#define LDSM_X4(r, addr) \
    asm volatile("ldmatrix.sync.aligned.m8n8.x4.shared.b16 {%0,%1,%2,%3}, [%4];" \
        : "=r"((r)[0]), "=r"((r)[1]), "=r"((r)[2]), "=r"((r)[3]) : "r"(addr))

// s8 MMA m16n8k32, s32 accum
__device__ __forceinline__ void mma_s8(int* d, const uint32_t* a, uint32_t b0, uint32_t b1) {
    asm volatile(
        "mma.sync.aligned.m16n8k32.row.col.s32.s8.s8.s32 "
        "{%0,%1,%2,%3}, {%4,%5,%6,%7}, {%8,%9}, {%0,%1,%2,%3};"
        : "+r"(d[0]), "+r"(d[1]), "+r"(d[2]), "+r"(d[3])
        : "r"(a[0]), "r"(a[1]), "r"(a[2]), "r"(a[3]), "r"(b0), "r"(b1));
}

// ---------------------------------------------------------------------------
// Small precompute kernels
// ---------------------------------------------------------------------------
__global__ void segstart_kernel(const int* __restrict__ segw, int M) {
    int s = threadIdx.x;
    if (s > NSEG) return;
    bool is64 = (segw[M - 1] == 0);   // int64: high half of last elem is 0
    int lo = 0, hi = M;
    while (lo < hi) {
        int mid = (lo + hi) >> 1;
        int v = is64 ? segw[2 * mid] : segw[mid];
        if (v < s) lo = mid + 1; else hi = mid;
    }
    g_segstart[s] = lo;
}

__global__ void rcp_init_kernel() {
    int i = blockIdx.x * blockDim.x + threadIdx.x;
    if (i < RCP_TAB) g_rcp[i] = 1.0f / (float)(i ? i : 1);
}

__global__ void weff_kernel(const float* __restrict__ Wk, const float* __restrict__ Wq) {
    int idx = blockIdx.x * blockDim.x + threadIdx.x;
    if (idx >= COMB * HEADS) return;
    int j = idx >> 3, h = idx & 7;
    const float* wk = Wk + (size_t)j * (HEADS * DPD) + h * DPD;
    const float* wq = Wq + h * DPD;
    float s = 0.f;
    #pragma unroll 8
    for (int d = 0; d < DPD; d++) s += wk[d] * wq[d];
    g_weff[idx] = s;
}

// ---------------------------------------------------------------------------
// Quantization helpers (round split: q = 256*ah + al, al zero-mean)
// ---------------------------------------------------------------------------
__global__ void quant_x_kernel(const float* __restrict__ X,
                               int8_t* __restrict__ qh, int8_t* __restrict__ ql,
                               float* __restrict__ s) {
    int row  = blockIdx.x * 8 + (threadIdx.x >> 5);
    int lane = threadIdx.x & 31;
    size_t base = (size_t)row * D_IN + lane * 4;
    float4 f = *(const float4*)(X + base);
    float v[4] = {f.x, f.y, f.z, f.w};
    float m = fmaxf(fmaxf(fabsf(v[0]), fabsf(v[1])), fmaxf(fabsf(v[2]), fabsf(v[3])));
    #pragma unroll
    for (int off = 16; off; off >>= 1) m = fmaxf(m, __shfl_xor_sync(~0u, m, off));
    float inv = m > 0.f ? 32512.f / m : 0.f;
    if (lane == 0) s[row] = m * (1.f / 32512.f);
    uint32_t wh = 0, wl = 0;
    #pragma unroll
    for (int b = 0; b < 4; b++) {
        int q  = __float2int_rn(v[b] * inv);
        int ah = (q + 128) >> 8;
        int al = q - (ah << 8);
        wh |= (uint32_t)(ah & 0xFF) << (8 * b);
        wl |= (uint32_t)(al & 0xFF) << (8 * b);
    }
    *(uint32_t*)(qh + base) = wh;
    *(uint32_t*)(ql + base) = wl;
}

// fp16 activation [M,512] -> int8 hi/lo planes + per-row scale (warp per row)
__global__ void quant_h_kernel(const __half* __restrict__ H,
                               int8_t* __restrict__ qh, int8_t* __restrict__ ql,
                               float* __restrict__ s) {
    int row  = blockIdx.x * 8 + (threadIdx.x >> 5);
    int lane = threadIdx.x & 31;
    size_t base = (size_t)row * WID + lane * 16;
    const __half2* hp = (const __half2*)(H + base);
    float v[16];
    #pragma unroll
    for (int p = 0; p < 8; p++) {
        float2 h2 = __half22float2(hp[p]);
        v[2 * p]     = h2.x;
        v[2 * p + 1] = h2.y;
    }
    float m = 0.f;
    #pragma unroll
    for (int i = 0; i < 16; i++) m = fmaxf(m, fabsf(v[i]));
    #pragma unroll
    for (int off = 16; off; off >>= 1) m = fmaxf(m, __shfl_xor_sync(~0u, m, off));
    float inv = m > 0.f ? 32512.f / m : 0.f;
    if (lane == 0) s[row] = m * (1.f / 32512.f);
    uint32_t ph[4], pl[4];
    #pragma unroll
    for (int g = 0; g < 4; g++) {
        uint32_t wh = 0, wl = 0;
        #pragma unroll
        for (int b = 0; b < 4; b++) {
            int q  = __float2int_rn(v[g * 4 + b] * inv);
            int ah = (q + 128) >> 8;
            int al = q - (ah << 8);
            wh |= (uint32_t)(ah & 0xFF) << (8 * b);
            wl |= (uint32_t)(al & 0xFF) << (8 * b);
        }
        ph[g] = wh; pl[g] = wl;
    }
    *(uint4*)(qh + base) = make_uint4(ph[0], ph[1], ph[2], ph[3]);
    *(uint4*)(ql + base) = make_uint4(pl[0], pl[1], pl[2], pl[3]);
}

__global__ void wquant_kernel(const float* __restrict__ W, int K,
                              int8_t* __restrict__ qh, int8_t* __restrict__ ql,
                              float* __restrict__ s) {
    int n = blockIdx.x;
    int tid = threadIdx.x;                 // 128 threads
    float m = 0.f;
    for (int k = tid; k < K; k += 128) m = fmaxf(m, fabsf(W[(size_t)k * WID + n]));
    __shared__ float red[128];
    red[tid] = m; __syncthreads();
    for (int st = 64; st; st >>= 1) {
        if (tid < st) red[tid] = fmaxf(red[tid], red[tid + st]);
        __syncthreads();
    }
    float mx = red[0];
    float inv = mx > 0.f ? 32512.f / mx : 0.f;
    if (tid == 0) s[n] = mx * (1.f / 32512.f);
    for (int k = tid; k < K; k += 128) {
        int q  = __float2int_rn(W[(size_t)k * WID + n] * inv);
        int ah = (q + 128) >> 8;
        qh[(size_t)n * K + k] = (int8_t)ah;
        ql[(size_t)n * K + k] = (int8_t)(q - (ah << 8));
    }
}

// ---------------------------------------------------------------------------
// INT8 split GEMM on mma.sync m16n8k32 (s32 accum).
//   Round-10 best config: CTA tile 128x64, 8 warps (4m x 2n), warp tile 32x32,
//   K-chunk 64, 3-stage cp.async ring, 2 CTA/SM, smem-staged coalesced epilogue.
//   MODE 0: Oh = fp16(relu(D + bias))        (single fp16 plane)
//   MODE 1: Oh = fp16(D)                      (z, no bias/relu)
//   acc1 = sum Ah*Bh ; acc2 = sum (Ah*Bl + Al*Bh)
//   D = sA[m]*sB[n]*(65536*acc1 + 256*acc2)
// ---------------------------------------------------------------------------
#define TS_B      80
#define A_TILE_B  (128 * TS_B)              // 10240
#define B_TILE_B  (64 * TS_B)               // 5120
#define ST_AH     0
#define ST_AL     (A_TILE_B)
#define ST_BH     (2 * A_TILE_B)
#define ST_BL     (2 * A_TILE_B + B_TILE_B)
#define STAGE_B   (2 * A_TILE_B + 2 * B_TILE_B)   // 30720
#define NSTAGE    3
#define GEMM_SMEM (NSTAGE * STAGE_B)               // 92160
#define EPI_STW   72                         // fp16 stride (144 B) for staging

template<int MODE>
__global__ __launch_bounds__(256, 2)
void s8_gemm(const int8_t* __restrict__ Ah, const int8_t* __restrict__ Al,
             const int8_t* __restrict__ Bh, const int8_t* __restrict__ Bl,
             const float* __restrict__ sA, const float* __restrict__ sB,
             const float* __restrict__ bias,
             __half* __restrict__ Oh, int K) {
    extern __shared__ char smem[];
    const uint32_t sb = smem_u32(smem);

    const int tid    = threadIdx.x;
    const int wid    = tid >> 5;
    const int lane   = tid & 31;
    const int warp_m = wid >> 1;          // 0..3 -> m offset 32*warp_m
    const int warp_n = wid & 1;           // 0..1 -> n offset 32*warp_n
    const int m0 = blockIdx.y * 128;      // x fastest -> A block shared in L2
    const int n0 = blockIdx.x * 64;

    // ---- load setup: per-thread pointers, advanced by +64 per chunk ----
    const int lr  = tid >> 2;             // 0..63
    const int lj  = (tid & 3) * 16;
    const size_t arowK = (size_t)64 * K;
    const int8_t* pAh = Ah + (size_t)(m0 + lr) * K + lj;
    const int8_t* pAl = Al + (size_t)(m0 + lr) * K + lj;
    const int8_t* pBh = Bh + (size_t)(n0 + lr) * K + lj;
    const int8_t* pBl = Bl + (size_t)(n0 + lr) * K + lj;
    const uint32_t dA0 = (uint32_t)(ST_AH + lr * TS_B + lj);
    const uint32_t dB0 = (uint32_t)(ST_BH + lr * TS_B + lj);

    // ---- compute setup ----
    const int lrow = lane & 15;
    const int lchk = (lane >> 4) * 16;
    const uint32_t aoff = (uint32_t)((warp_m * 32 + lrow) * TS_B + lchk);
    const uint32_t boff = (uint32_t)((warp_n * 32 + lrow) * TS_B + lchk);

    int acc1[2][4][4], acc2[2][4][4];
    #pragma unroll
    for (int i = 0; i < 2; i++)
        #pragma unroll
        for (int j = 0; j < 4; j++)
            #pragma unroll
            for (int q = 0; q < 4; q++) { acc1[i][j][q] = 0; acc2[i][j][q] = 0; }

    const int nch = K >> 6;               // 64-int8 chunks

    #define ISSUE_CHUNK(stg) do {                                   \
        uint32_t _b = sb + (stg) * STAGE_B;                         \
        CP_ASYNC16(_b + dA0,              pAh);                     \
        CP_ASYNC16(_b + dA0 + 64 * TS_B,  pAh + arowK);             \
        CP_ASYNC16(_b + dA0 + A_TILE_B,            pAl);            \
        CP_ASYNC16(_b + dA0 + A_TILE_B + 64 * TS_B, pAl + arowK);   \
        CP_ASYNC16(_b + dB0,              pBh);                     \
        CP_ASYNC16(_b + dB0 + B_TILE_B,   pBl);                     \
        pAh += 64; pAl += 64; pBh += 64; pBl += 64;                 \
        CP_COMMIT();                                                \
    } while (0)

    ISSUE_CHUNK(0);
    if (nch > 1) ISSUE_CHUNK(1);

    int stg = 0;
    for (int c = 0; c < nch; c++) {
        if (c + 1 < nch) CP_WAIT1(); else CP_WAIT0();
        __syncthreads();                  // single sync per chunk
        if (c + 2 < nch) {
            int ns = stg + 2; if (ns >= NSTAGE) ns -= NSTAGE;
            ISSUE_CHUNK(ns);
        }

        const uint32_t stage = sb + stg * STAGE_B;
        const uint32_t sAh = stage + ST_AH + aoff;
        const uint32_t sAl = stage + ST_AL + aoff;
        const uint32_t sBh = stage + ST_BH + boff;
        const uint32_t sBl = stage + ST_BL + boff;
        #pragma unroll
        for (int ks = 0; ks < 2; ks++) {
            uint32_t bh_[2][4], bl_[2][4], ah_[2][4], al_[2][4];
            #pragma unroll
            for (int g = 0; g < 2; g++)
                LDSM_X4(bh_[g], sBh + g * (16 * TS_B) + ks * 32);
            #pragma unroll
            for (int mb = 0; mb < 2; mb++)
                LDSM_X4(ah_[mb], sAh + mb * (16 * TS_B) + ks * 32);
            #pragma unroll
            for (int g = 0; g < 2; g++)
                LDSM_X4(bl_[g], sBl + g * (16 * TS_B) + ks * 32);
            #pragma unroll
            for (int mb = 0; mb < 2; mb++)
                LDSM_X4(al_[mb], sAl + mb * (16 * TS_B) + ks * 32);

            #pragma unroll
            for (int mb = 0; mb < 2; mb++)
                #pragma unroll
                for (int nb = 0; nb < 4; nb++) {
                    const int g = nb >> 1, p = nb & 1;
                    mma_s8(acc1[mb][nb], ah_[mb], bh_[g][p], bh_[g][p + 2]);
                }
            #pragma unroll
            for (int mb = 0; mb < 2; mb++)
                #pragma unroll
                for (int nb = 0; nb < 4; nb++) {
                    const int g = nb >> 1, p = nb & 1;
                    mma_s8(acc2[mb][nb], ah_[mb], bl_[g][p], bl_[g][p + 2]);
                }
            #pragma unroll
            for (int mb = 0; mb < 2; mb++)
                #pragma unroll
                for (int nb = 0; nb < 4; nb++) {
                    const int g = nb >> 1, p = nb & 1;
                    mma_s8(acc2[mb][nb], al_[mb], bh_[g][p], bh_[g][p + 2]);
                }
        }
        if (++stg == NSTAGE) stg = 0;
    }
    #undef ISSUE_CHUNK

    // ---------------- Epilogue (smem-staged, coalesced fp16 stores) --------
    const int gid  = lane >> 2;
    const int tid4 = lane & 3;
    float sa[2][2];
    #pragma unroll
    for (int mb = 0; mb < 2; mb++)
        #pragma unroll
        for (int half = 0; half < 2; half++)
            sa[mb][half] = sA[m0 + warp_m * 32 + mb * 16 + gid + half * 8];

    __syncthreads();                      // mainloop done; reuse stage smem
    __half* sh = (__half*)smem;

    #pragma unroll
    for (int nb = 0; nb < 4; nb++) {
        const int cc  = warp_n * 32 + nb * 8 + tid4 * 2;
        const int col = n0 + cc;
        const float sb0 = sB[col], sb1 = sB[col + 1];
        float b0 = 0.f, b1 = 0.f;
        if (MODE == 0) { b0 = bias[col]; b1 = bias[col + 1]; }
        #pragma unroll
        for (int mb = 0; mb < 2; mb++) {
            #pragma unroll
            for (int half = 0; half < 2; half++) {
                const int r = warp_m * 32 + mb * 16 + gid + half * 8;
                const float ss = sa[mb][half];
                float d0 = ss * sb0 * (65536.f * (float)acc1[mb][nb][2 * half]
                                       + 256.f * (float)acc2[mb][nb][2 * half]);
                float d1 = ss * sb1 * (65536.f * (float)acc1[mb][nb][2 * half + 1]
                                       + 256.f * (float)acc2[mb][nb][2 * half + 1]);
                if (MODE == 0) {
                    d0 = fmaxf(d0 + b0, 0.f);
                    d1 = fmaxf(d1 + b1, 0.f);
                }
                *(__half2*)(sh + r * EPI_STW + cc) = __floats2half2_rn(d0, d1);
            }
        }
    }
    __syncthreads();

    // copy-out: warp owns 16 rows; per instr 8 lanes cover one 128B row
    const int rrow = lane >> 3;           // 0..3
    const int c16  = lane & 7;            // 16B chunk in row
    #pragma unroll
    for (int it = 0; it < 4; it++) {
        const int r = wid * 16 + it * 4 + rrow;
        const uint4 vh = *(const uint4*)(sh + r * EPI_STW + c16 * 8);
        const size_t gbase = (size_t)(m0 + r) * WID + n0 + c16 * 8;
        *(uint4*)(Oh + gbase) = vh;
    }
}

// ---------------------------------------------------------------------------
// Segmented prefix-mean + bias + relu (z fp16 -> agg fp16; fp32 accumulate)
// ---------------------------------------------------------------------------
__global__ void scan_kernel(const __half* __restrict__ Z, const float* __restrict__ br,
                            __half* __restrict__ Agg) {
    int seg = blockIdx.x;
    int col = blockIdx.y * blockDim.x + threadIdx.x;
    int s = g_segstart[seg];
    int e = g_segstart[seg + 1];
    float b = br[col];
    float run = 0.f;
    for (int n = s; n < e; n++) {
        run += __half2float(Z[(size_t)n * WID + col]);
        int cnt = n - s + 1;
        float m = (cnt < RCP_TAB) ? run * g_rcp[cnt] : run / (float)cnt;
        Agg[(size_t)n * WID + col] = __float2half(fmaxf(m + b, 0.f));
    }
}

// ---------------------------------------------------------------------------
// Final projection: out[n,h] = ([X, agg] @ w_eff)[n,h] / sqrt(DPD)
// ---------------------------------------------------------------------------
__global__ __launch_bounds__(256)
void final_kernel(const float* __restrict__ X, const __half* __restrict__ Agg,
                  float* __restrict__ out, int M) {
    __shared__ float ws[HEADS * COMB];
    for (int i = threadIdx.x; i < COMB * HEADS; i += blockDim.x) {
        int j = i >> 3, h = i & 7;
        ws[h * COMB + j] = g_weff[i];
    }
    __syncthreads();

    int warp = threadIdx.x >> 5;
    int lane = threadIdx.x & 31;
    int row  = blockIdx.x * 8 + warp;
    if (row >= M) return;

    const float*  xr = X   + (size_t)row * D_IN;
    const __half* ar = Agg + (size_t)row * WID;

    float acc[HEADS];
    #pragma unroll
    for (int h = 0; h < HEADS; h++) acc[h] = 0.f;

    #pragma unroll
    for (int t = 0; t < D_IN / 32; t++) {
        int j = t * 32 + lane;
        float v = xr[j];
        #pragma unroll
        for (int h = 0; h < HEADS; h++) acc[h] = fmaf(v, ws[h * COMB + j], acc[h]);
    }
    #pragma unroll
    for (int t = 0; t < WID / 32; t++) {
        int j = t * 32 + lane;
        float v = __half2float(ar[j]);
        #pragma unroll
        for (int h = 0; h < HEADS; h++) acc[h] = fmaf(v, ws[h * COMB + D_IN + j], acc[h]);
    }

    #pragma unroll
    for (int off = 16; off; off >>= 1)
        #pragma unroll
        for (int h = 0; h < HEADS; h++)
            acc[h] += __shfl_xor_sync(0xffffffffu, acc[h], off);

    if (lane < HEADS)
        out[(size_t)row * HEADS + lane] = acc[lane] * 0.08838834764831844f;
}

// ---------------------------------------------------------------------------
// Launch
// ---------------------------------------------------------------------------
extern "C" void kernel_launch(void* const* d_in, const int* in_sizes, int n_in,
                              void* d_out, int out_size) {
    const float* X   = (const float*)d_in[0];
    const int*   seg = (const int*)  d_in[1];
    const float* W1  = (const float*)d_in[2];
    const float* b1  = (const float*)d_in[3];
    const float* W2  = (const float*)d_in[4];
    const float* b2  = (const float*)d_in[5];
    const float* W3  = (const float*)d_in[6];
    const float* b3  = (const float*)d_in[7];
    const float* Wr  = (const float*)d_in[8];
    const float* br  = (const float*)d_in[9];
    const float* Wk  = (const float*)d_in[10];
    const float* Wq  = (const float*)d_in[11];
    float* out = (float*)d_out;

    const int M = in_sizes[0] / D_IN;

    int8_t *x8h, *x8l, *a8h, *a8l;
    int8_t *w1h, *w1l, *w2h, *w2l, *w3h, *w3l, *wrh, *wrl;
    __half *h16, *z16, *agg16;
    float *sx, *sa, *sw1, *sw2, *sw3, *sw4;
    cudaGetSymbolAddress((void**)&x8h, g_x8h); cudaGetSymbolAddress((void**)&x8l, g_x8l);
    cudaGetSymbolAddress((void**)&a8h, g_a8h); cudaGetSymbolAddress((void**)&a8l, g_a8l);
    cudaGetSymbolAddress((void**)&h16, g_h16);
    cudaGetSymbolAddress((void**)&z16, g_z16);
    cudaGetSymbolAddress((void**)&agg16, g_agg16);
    cudaGetSymbolAddress((void**)&w1h, g_w1h); cudaGetSymbolAddress((void**)&w1l, g_w1l);
    cudaGetSymbolAddress((void**)&w2h, g_w2h); cudaGetSymbolAddress((void**)&w2l, g_w2l);
    cudaGetSymbolAddress((void**)&w3h, g_w3h); cudaGetSymbolAddress((void**)&w3l, g_w3l);
    cudaGetSymbolAddress((void**)&wrh, g_wrh); cudaGetSymbolAddress((void**)&wrl, g_wrl);
    cudaGetSymbolAddress((void**)&sx,  g_sx);  cudaGetSymbolAddress((void**)&sa,  g_sa);
    cudaGetSymbolAddress((void**)&sw1, g_sw1); cudaGetSymbolAddress((void**)&sw2, g_sw2);
    cudaGetSymbolAddress((void**)&sw3, g_sw3); cudaGetSymbolAddress((void**)&sw4, g_sw4);

    cudaFuncSetAttribute(s8_gemm<0>, cudaFuncAttributeMaxDynamicSharedMemorySize, GEMM_SMEM);
    cudaFuncSetAttribute(s8_gemm<1>, cudaFuncAttributeMaxDynamicSharedMemorySize, GEMM_SMEM);

    const dim3 ggrid(WID / 64, M / 128);   // x fastest: 8 N-blocks share an A block

    quant_x_kernel<<<M / 8, 256>>>(X, x8h, x8l, sx);
    wquant_kernel<<<WID, 128>>>(W1, D_IN, w1h, w1l, sw1);
    rcp_init_kernel<<<RCP_TAB / 256, 256>>>();

    // h1 = relu(X @ W1 + b1) -> fp16
    s8_gemm<0><<<ggrid, 256, GEMM_SMEM>>>(x8h, x8l, w1h, w1l, sx, sw1, b1, h16, D_IN);
    quant_h_kernel<<<M / 8, 256>>>(h16, a8h, a8l, sa);
    wquant_kernel<<<WID, 128>>>(W2, WID, w2h, w2l, sw2);

    // h2 = relu(h1 @ W2 + b2)
    s8_gemm<0><<<ggrid, 256, GEMM_SMEM>>>(a8h, a8l, w2h, w2l, sa, sw2, b2, h16, WID);
    quant_h_kernel<<<M / 8, 256>>>(h16, a8h, a8l, sa);
    wquant_kernel<<<WID, 128>>>(W3, WID, w3h, w3l, sw3);

    // enc = relu(h2 @ W3 + b3)
    s8_gemm<0><<<ggrid, 256, GEMM_SMEM>>>(a8h, a8l, w3h, w3l, sa, sw3, b3, h16, WID);
    quant_h_kernel<<<M / 8, 256>>>(h16, a8h, a8l, sa);
    wquant_kernel<<<WID, 128>>>(Wr, WID, wrh, wrl, sw4);

    // z = enc @ Wr (fp16; bias+relu after scan — scan commutes with Wr)
    s8_gemm<1><<<ggrid, 256, GEMM_SMEM>>>(a8h, a8l, wrh, wrl, sa, sw4, nullptr, z16, WID);

    segstart_kernel<<<1, NSEG + 1>>>(seg, M);
    weff_kernel<<<(COMB * HEADS + 127) / 128, 128>>>(Wk, Wq);

    // agg = relu(cumseg_mean(z) + br)
    scan_kernel<<<dim3(NSEG, WID / 256), 256>>>(z16, br, agg16);

    // out = [X, agg] @ w_eff / sqrt(DPD)
    final_kernel<<<M / 8, 256>>>(X, agg16, out, M);
}

// round 13
// speedup vs baseline: 1.4775x; 1.2716x over previous
#include <cuda_runtime.h>
#include <cuda_fp16.h>
#include <cstdint>

// ---------------------------------------------------------------------------
// Problem constants
// ---------------------------------------------------------------------------
#define D_IN   128
#define WID    512
#define NSEG   256
#define HEADS  8
#define DPD    128
#define COMB   (D_IN + WID)
#define RCP_TAB 4096
#define NMAX 131072

// ---------------------------------------------------------------------------
// Device global scratch (no runtime allocation)
// ---------------------------------------------------------------------------
__device__ __half g_x16[(size_t)NMAX * D_IN];
__device__ __half g_hA[(size_t)NMAX * WID];
__device__ __half g_hB[(size_t)NMAX * WID];
__device__ __half g_z16[(size_t)NMAX * WID];
__device__ __half g_agg16[(size_t)NMAX * WID];
__device__ __half g_w1t[WID * D_IN];
__device__ __half g_w2t[WID * WID];
__device__ __half g_w3t[WID * WID];
__device__ __half g_wrt[WID * WID];
__device__ float g_weff[COMB * HEADS];
__device__ int   g_segstart[NSEG + 1];
__device__ float g_rcp[RCP_TAB];

// ---------------------------------------------------------------------------
// PTX primitives (non-arch-specific; valid on plain sm_100)
// ---------------------------------------------------------------------------
__device__ __forceinline__ uint32_t smem_u32(const void* p) {
    uint32_t a;
    asm("{ .reg .u64 t; cvta.to.shared.u64 t, %1; cvt.u32.u64 %0, t; }" : "=r"(a) : "l"(p));
    return a;
}

#define CP_ASYNC16(dst, src) \
    asm volatile("cp.async.cg.shared.global [%0], [%1], 16;" :: "r"(dst), "l"(src))
#define CP_COMMIT() asm volatile("cp.async.commit_group;" ::: "memory")
#define CP_WAIT1()  asm volatile("cp.async.wait_group 1;" ::: "memory")
#define CP_WAIT0()  asm volatile("cp.async.wait_group 0;" ::: "memory")

#define LDSM_X4(r, addr) \
    asm volatile("ldmatrix.sync.aligned.m8n8.x4.shared.b16 {%0,%1,%2,%3}, [%4];" \
        : "=r"((r)[0]), "=r"((r)[1]), "=r"((r)[2]), "=r"((r)[3]) : "r"(addr))

// fp16 MMA m16n8k16, fp32 accum (fragment layout identical to validated bf16)
__device__ __forceinline__ void mma_f16(float* d, const uint32_t* a, uint32_t b0, uint32_t b1) {
    asm volatile(
        "mma.sync.aligned.m16n8k16.row.col.f32.f16.f16.f32 "
        "{%0,%1,%2,%3}, {%4,%5,%6,%7}, {%8,%9}, {%0,%1,%2,%3};"
        : "+f"(d[0]), "+f"(d[1]), "+f"(d[2]), "+f"(d[3])
        : "r"(a[0]), "r"(a[1]), "r"(a[2]), "r"(a[3]), "r"(b0), "r"(b1));
}

// ---------------------------------------------------------------------------
// Small precompute kernels
// ---------------------------------------------------------------------------
__global__ void segstart_kernel(const int* __restrict__ segw, int M) {
    int s = threadIdx.x;
    if (s > NSEG) return;
    bool is64 = (segw[M - 1] == 0);   // int64: high half of last elem is 0
    int lo = 0, hi = M;
    while (lo < hi) {
        int mid = (lo + hi) >> 1;
        int v = is64 ? segw[2 * mid] : segw[mid];
        if (v < s) lo = mid + 1; else hi = mid;
    }
    g_segstart[s] = lo;
}

__global__ void rcp_init_kernel() {
    int i = blockIdx.x * blockDim.x + threadIdx.x;
    if (i < RCP_TAB) g_rcp[i] = 1.0f / (float)(i ? i : 1);
}

__global__ void weff_kernel(const float* __restrict__ Wk, const float* __restrict__ Wq) {
    int idx = blockIdx.x * blockDim.x + threadIdx.x;
    if (idx >= COMB * HEADS) return;
    int j = idx >> 3, h = idx & 7;
    const float* wk = Wk + (size_t)j * (HEADS * DPD) + h * DPD;
    const float* wq = Wq + h * DPD;
    float s = 0.f;
    #pragma unroll 8
    for (int d = 0; d < DPD; d++) s += wk[d] * wq[d];
    g_weff[idx] = s;
}

// X fp32 -> fp16 (vectorized)
__global__ void xcvt_kernel(const float* __restrict__ X, __half* __restrict__ O, size_t n4) {
    size_t i = (size_t)blockIdx.x * blockDim.x + threadIdx.x;
    if (i >= n4) return;
    float4 v = ((const float4*)X)[i];
    __half2 a = __floats2half2_rn(v.x, v.y);
    __half2 b = __floats2half2_rn(v.z, v.w);
    ((__half2*)O)[2 * i]     = a;
    ((__half2*)O)[2 * i + 1] = b;
}

// W [K, 512] fp32 -> Wt [512, K] fp16 (transpose + convert)
__global__ void wcvt_kernel(const float* __restrict__ W, __half* __restrict__ Wt, int K) {
    int i = blockIdx.x * blockDim.x + threadIdx.x;
    if (i >= WID * K) return;
    int n = i / K, k = i % K;
    Wt[i] = __float2half(W[(size_t)k * WID + n]);
}

// ---------------------------------------------------------------------------
// fp16 GEMM on mma.sync m16n8k16 (fp32 accum), single product.
//   CTA tile 128x128, 8 warps (4m x 2n), warp tile 32x64, K-chunk 32 elems,
//   3-stage cp.async ring, 2 CTA/SM, smem-staged coalesced fp16 epilogue.
//   MODE 0: Oh = fp16(relu(D + bias)) ; MODE 1: Oh = fp16(D)
// smem rows: 32 fp16 = 64 B padded to TS_B=80 (conflict-free ldsm).
// ---------------------------------------------------------------------------
#define TS_B      80
#define T128_B    (128 * TS_B)              // 10240 per operand tile
#define ST_A      0
#define ST_B      (T128_B)
#define STAGE_B   (2 * T128_B)              // 20480
#define NSTAGE    3
#define GEMM_SMEM (NSTAGE * STAGE_B)        // 61440
#define EPI_STW   136                       // fp16 stride (272 B) for staging

template<int MODE>
__global__ __launch_bounds__(256, 2)
void f16_gemm(const __half* __restrict__ A, const __half* __restrict__ B,
              const float* __restrict__ bias, __half* __restrict__ Oh, int K) {
    extern __shared__ char smem[];
    const uint32_t sb = smem_u32(smem);

    const int tid    = threadIdx.x;
    const int wid    = tid >> 5;
    const int lane   = tid & 31;
    const int warp_m = wid >> 1;          // 0..3 -> m offset 32*warp_m
    const int warp_n = wid & 1;           // 0..1 -> n offset 64*warp_n
    const int m0 = blockIdx.y * 128;      // x fastest -> A panel shared in L2
    const int n0 = blockIdx.x * 128;

    // ---- load setup: 4 cp.async per thread per chunk; ptr += 32 elems ----
    const int lr = tid >> 1;              // 0..127 row
    const int lj = (tid & 1) * 2;         // 16B chunk pair base {0,1} or {2,3}
    const __half* pA = A + (size_t)(m0 + lr) * K + lj * 8;
    const __half* pB = B + (size_t)(n0 + lr) * K + lj * 8;
    const uint32_t dA0 = (uint32_t)(ST_A + lr * TS_B + lj * 16);
    const uint32_t dB0 = (uint32_t)(ST_B + lr * TS_B + lj * 16);

    // ---- compute setup ----
    const int lrow = lane & 15;
    const int lchk = (lane >> 4) * 16;
    const uint32_t aoff = (uint32_t)((warp_m * 32 + lrow) * TS_B + lchk);
    const uint32_t boff = (uint32_t)((warp_n * 64 + lrow) * TS_B + lchk);

    float acc[2][8][4];                   // [mb 16][nb n8][frag]
    #pragma unroll
    for (int i = 0; i < 2; i++)
        #pragma unroll
        for (int j = 0; j < 8; j++)
            #pragma unroll
            for (int q = 0; q < 4; q++) acc[i][j][q] = 0.f;

    const int nch = K >> 5;               // 32-elem chunks

    #define ISSUE_CHUNK(stg) do {                          \
        uint32_t _b = sb + (stg) * STAGE_B;                \
        CP_ASYNC16(_b + dA0,      pA);                     \
        CP_ASYNC16(_b + dA0 + 16, pA + 8);                 \
        CP_ASYNC16(_b + dB0,      pB);                     \
        CP_ASYNC16(_b + dB0 + 16, pB + 8);                 \
        pA += 32; pB += 32;                                \
        CP_COMMIT();                                       \
    } while (0)

    ISSUE_CHUNK(0);
    if (nch > 1) ISSUE_CHUNK(1);

    int stg = 0;
    for (int c = 0; c < nch; c++) {
        if (c + 1 < nch) CP_WAIT1(); else CP_WAIT0();
        __syncthreads();                  // single sync per chunk
        if (c + 2 < nch) {
            int ns = stg + 2; if (ns >= NSTAGE) ns -= NSTAGE;
            ISSUE_CHUNK(ns);
        }

        const uint32_t stage = sb + stg * STAGE_B;
        const uint32_t sA = stage + ST_A + aoff;
        const uint32_t sB_ = stage + ST_B + boff;
        #pragma unroll
        for (int ks = 0; ks < 2; ks++) {  // two k16 steps per 32-elem chunk
            uint32_t bh[4][4], af[2][4];
            #pragma unroll
            for (int g = 0; g < 4; g++)
                LDSM_X4(bh[g], sB_ + g * (16 * TS_B) + ks * 32);
            #pragma unroll
            for (int mb = 0; mb < 2; mb++)
                LDSM_X4(af[mb], sA + mb * (16 * TS_B) + ks * 32);

            #pragma unroll
            for (int mb = 0; mb < 2; mb++)
                #pragma unroll
                for (int nb = 0; nb < 8; nb++) {
                    const int g = nb >> 1, p = nb & 1;
                    mma_f16(acc[mb][nb], af[mb], bh[g][p], bh[g][p + 2]);
                }
        }
        if (++stg == NSTAGE) stg = 0;
    }
    #undef ISSUE_CHUNK

    // ---------------- Epilogue (smem-staged, coalesced fp16 stores) --------
    const int gid  = lane >> 2;
    const int tid4 = lane & 3;

    __syncthreads();                      // mainloop done; reuse stage smem
    __half* sh = (__half*)smem;

    #pragma unroll
    for (int nb = 0; nb < 8; nb++) {
        const int cc  = warp_n * 64 + nb * 8 + tid4 * 2;
        const int col = n0 + cc;
        float b0 = 0.f, b1 = 0.f;
        if (MODE == 0) { b0 = bias[col]; b1 = bias[col + 1]; }
        #pragma unroll
        for (int mb = 0; mb < 2; mb++) {
            #pragma unroll
            for (int half = 0; half < 2; half++) {
                const int r = warp_m * 32 + mb * 16 + gid + half * 8;
                float d0 = acc[mb][nb][2 * half];
                float d1 = acc[mb][nb][2 * half + 1];
                if (MODE == 0) {
                    d0 = fmaxf(d0 + b0, 0.f);
                    d1 = fmaxf(d1 + b1, 0.f);
                }
                *(__half2*)(sh + r * EPI_STW + cc) = __floats2half2_rn(d0, d1);
            }
        }
    }
    __syncthreads();

    // copy-out: warp owns 16 rows; per iter 2 rows x 16 chunks of 16B
    const int rhalf = lane >> 4;          // 0..1
    const int c16   = lane & 15;          // 16B chunk in 256B row
    #pragma unroll
    for (int it = 0; it < 8; it++) {
        const int r = wid * 16 + it * 2 + rhalf;
        const uint4 vh = *(const uint4*)(sh + r * EPI_STW + c16 * 8);
        const size_t gbase = (size_t)(m0 + r) * WID + n0 + c16 * 8;
        *(uint4*)(Oh + gbase) = vh;
    }
}

// ---------------------------------------------------------------------------
// Segmented prefix-mean + bias + relu (z fp16 -> agg fp16; fp32 accumulate)
// ---------------------------------------------------------------------------
__global__ void scan_kernel(const __half* __restrict__ Z, const float* __restrict__ br,
                            __half* __restrict__ Agg) {
    int seg = blockIdx.x;
    int col = blockIdx.y * blockDim.x + threadIdx.x;
    int s = g_segstart[seg];
    int e = g_segstart[seg + 1];
    float b = br[col];
    float run = 0.f;
    for (int n = s; n < e; n++) {
        run += __half2float(Z[(size_t)n * WID + col]);
        int cnt = n - s + 1;
        float m = (cnt < RCP_TAB) ? run * g_rcp[cnt] : run / (float)cnt;
        Agg[(size_t)n * WID + col] = __float2half(fmaxf(m + b, 0.f));
    }
}

// ---------------------------------------------------------------------------
// Final projection: out[n,h] = ([X, agg] @ w_eff)[n,h] / sqrt(DPD)
// ---------------------------------------------------------------------------
__global__ __launch_bounds__(256)
void final_kernel(const float* __restrict__ X, const __half* __restrict__ Agg,
                  float* __restrict__ out, int M) {
    __shared__ float ws[HEADS * COMB];
    for (int i = threadIdx.x; i < COMB * HEADS; i += blockDim.x) {
        int j = i >> 3, h = i & 7;
        ws[h * COMB + j] = g_weff[i];
    }
    __syncthreads();

    int warp = threadIdx.x >> 5;
    int lane = threadIdx.x & 31;
    int row  = blockIdx.x * 8 + warp;
    if (row >= M) return;

    const float*  xr = X   + (size_t)row * D_IN;
    const __half* ar = Agg + (size_t)row * WID;

    float acc[HEADS];
    #pragma unroll
    for (int h = 0; h < HEADS; h++) acc[h] = 0.f;

    #pragma unroll
    for (int t = 0; t < D_IN / 32; t++) {
        int j = t * 32 + lane;
        float v = xr[j];
        #pragma unroll
        for (int h = 0; h < HEADS; h++) acc[h] = fmaf(v, ws[h * COMB + j], acc[h]);
    }
    #pragma unroll
    for (int t = 0; t < WID / 32; t++) {
        int j = t * 32 + lane;
        float v = __half2float(ar[j]);
        #pragma unroll
        for (int h = 0; h < HEADS; h++) acc[h] = fmaf(v, ws[h * COMB + D_IN + j], acc[h]);
    }

    #pragma unroll
    for (int off = 16; off; off >>= 1)
        #pragma unroll
        for (int h = 0; h < HEADS; h++)
            acc[h] += __shfl_xor_sync(0xffffffffu, acc[h], off);

    if (lane < HEADS)
        out[(size_t)row * HEADS + lane] = acc[lane] * 0.08838834764831844f;
}

// ---------------------------------------------------------------------------
// Launch
// ---------------------------------------------------------------------------
extern "C" void kernel_launch(void* const* d_in, const int* in_sizes, int n_in,
                              void* d_out, int out_size) {
    const float* X   = (const float*)d_in[0];
    const int*   seg = (const int*)  d_in[1];
    const float* W1  = (const float*)d_in[2];
    const float* b1  = (const float*)d_in[3];
    const float* W2  = (const float*)d_in[4];
    const float* b2  = (const float*)d_in[5];
    const float* W3  = (const float*)d_in[6];
    const float* b3  = (const float*)d_in[7];
    const float* Wr  = (const float*)d_in[8];
    const float* br  = (const float*)d_in[9];
    const float* Wk  = (const float*)d_in[10];
    const float* Wq  = (const float*)d_in[11];
    float* out = (float*)d_out;

    const int M = in_sizes[0] / D_IN;

    __half *x16, *hA, *hB, *z16, *agg16, *w1t, *w2t, *w3t, *wrt;
    cudaGetSymbolAddress((void**)&x16, g_x16);
    cudaGetSymbolAddress((void**)&hA,  g_hA);
    cudaGetSymbolAddress((void**)&hB,  g_hB);
    cudaGetSymbolAddress((void**)&z16, g_z16);
    cudaGetSymbolAddress((void**)&agg16, g_agg16);
    cudaGetSymbolAddress((void**)&w1t, g_w1t);
    cudaGetSymbolAddress((void**)&w2t, g_w2t);
    cudaGetSymbolAddress((void**)&w3t, g_w3t);
    cudaGetSymbolAddress((void**)&wrt, g_wrt);

    cudaFuncSetAttribute(f16_gemm<0>, cudaFuncAttributeMaxDynamicSharedMemorySize, GEMM_SMEM);
    cudaFuncSetAttribute(f16_gemm<1>, cudaFuncAttributeMaxDynamicSharedMemorySize, GEMM_SMEM);

    const dim3 ggrid(WID / 128, M / 128);  // x fastest: 4 N-blocks share an A panel

    xcvt_kernel<<<(unsigned)(((size_t)M * D_IN / 4 + 255) / 256), 256>>>(X, x16, (size_t)M * D_IN / 4);
    wcvt_kernel<<<(WID * D_IN + 255) / 256, 256>>>(W1, w1t, D_IN);
    rcp_init_kernel<<<RCP_TAB / 256, 256>>>();

    // h1 = relu(X @ W1 + b1)
    f16_gemm<0><<<ggrid, 256, GEMM_SMEM>>>(x16, w1t, b1, hA, D_IN);
    wcvt_kernel<<<(WID * WID + 255) / 256, 256>>>(W2, w2t, WID);

    // h2 = relu(h1 @ W2 + b2)
    f16_gemm<0><<<ggrid, 256, GEMM_SMEM>>>(hA, w2t, b2, hB, WID);
    wcvt_kernel<<<(WID * WID + 255) / 256, 256>>>(W3, w3t, WID);

    // enc = relu(h2 @ W3 + b3)
    f16_gemm<0><<<ggrid, 256, GEMM_SMEM>>>(hB, w3t, b3, hA, WID);
    wcvt_kernel<<<(WID * WID + 255) / 256, 256>>>(Wr, wrt, WID);

    // z = enc @ Wr (bias+relu after scan — scan commutes with Wr)
    f16_gemm<1><<<ggrid, 256, GEMM_SMEM>>>(hA, wrt, nullptr, z16, WID);

    segstart_kernel<<<1, NSEG + 1>>>(seg, M);
    weff_kernel<<<(COMB * HEADS + 127) / 128, 128>>>(Wk, Wq);

    // agg = relu(cumseg_mean(z) + br)
    scan_kernel<<<dim3(NSEG, WID / 256), 256>>>(z16, br, agg16);

    // out = [X, agg] @ w_eff / sqrt(DPD)
    final_kernel<<<M / 8, 256>>>(X, agg16, out, M);
}